// round 1
// baseline (speedup 1.0000x reference)
#include <cuda_runtime.h>

#define NBATCH 2048
#define DIM 512
#define NCLS 62
#define THREADS 1024
#define ROW4 128              // float4 per 512-float row
#define TOT4 (62 * ROW4)      // float4 per batch across all 62 channels

// smem channel c (0..61, concat order x1|x2|x3|x4) -> output row in trans
__constant__ int c_orow[62] = {
    // G1 (x1 channels 0..11)
    1, 0, 2, 3, 4, 6, 7, 8, 9, 10, 11, 12,
    // G2 (x2 channels 0..17)
    5, 13, 14, 15, 21, 22, 23, 24, 30, 31, 32, 33, 39, 40, 41, 42, 48, 49,
    // G3 (x3 channels 0..19)
    16, 17, 18, 19, 20, 25, 26, 27, 28, 29, 34, 35, 36, 37, 38, 43, 44, 45, 46, 47,
    // G4 (x4 channels 0..11)
    50, 51, 52, 53, 54, 55, 56, 57, 58, 59, 60, 61
};
__constant__ int c_gi[62] = {
    0,0,0,0,0,0,0,0,0,0,0,0,
    1,1,1,1,1,1,1,1,1,1,1,1,1,1,1,1,1,1,
    2,2,2,2,2,2,2,2,2,2,2,2,2,2,2,2,2,2,2,2,
    3,3,3,3,3,3,3,3,3,3,3,3
};

__global__ __launch_bounds__(THREADS, 1)
void lgl_fused_kernel(
    const float* __restrict__ x1, const float* __restrict__ x2,
    const float* __restrict__ x3, const float* __restrict__ x4,
    const float* __restrict__ g,
    const float* __restrict__ l1, const float* __restrict__ l2,
    const float* __restrict__ l3, const float* __restrict__ l4,
    const float* __restrict__ W1, const float* __restrict__ b1,
    const float* __restrict__ W2, const float* __restrict__ b2,
    const float* __restrict__ W3, const float* __restrict__ b3,
    const float* __restrict__ W4, const float* __restrict__ b4,
    float* __restrict__ out)
{
    extern __shared__ float4 sx[];        // 62*128 float4 = 126976 B
    __shared__ float red[32][4];
    __shared__ float s_dot[4];
    __shared__ float s_conf[4];
    __shared__ float s_uf[4];

    const int b    = blockIdx.x;
    const int tid  = threadIdx.x;
    const int lane = tid & 31;
    const int warp = tid >> 5;

    const float* xs[4] = { x1, x2, x3, x4 };
    const float* Ws[4] = { W1, W2, W3, W4 };
    const float* bs[4] = { b1, b2, b3, b4 };
    const float* ls[4] = { l1, l2, l3, l4 };
    const int ch[4]   = { 12, 18, 20, 12 };
    const int base[4] = { 0, 12, 30, 50 };

    // ---- Phase 1: stream x -> smem while accumulating dot(x_i, W_i) ----
    float part[4] = { 0.f, 0.f, 0.f, 0.f };
#pragma unroll
    for (int i = 0; i < 4; i++) {
        const int n4 = ch[i] * ROW4;
        const float4* xg = (const float4*)xs[i] + (size_t)b * n4;
        const float4* wg = (const float4*)Ws[i];
        float4* dst = sx + base[i] * ROW4;
        for (int t = tid; t < n4; t += THREADS) {
            float4 v = xg[t];
            float4 w = wg[t];
            dst[t] = v;
            part[i] += v.x * w.x + v.y * w.y + v.z * w.z + v.w * w.w;
        }
    }
#pragma unroll
    for (int i = 0; i < 4; i++)
#pragma unroll
        for (int o = 16; o > 0; o >>= 1)
            part[i] += __shfl_xor_sync(0xffffffffu, part[i], o);
    if (lane == 0) {
#pragma unroll
        for (int i = 0; i < 4; i++) red[warp][i] = part[i];
    }
    __syncthreads();

    if (warp == 0) {
        float v0 = red[lane][0], v1 = red[lane][1], v2 = red[lane][2], v3 = red[lane][3];
#pragma unroll
        for (int o = 16; o > 0; o >>= 1) {
            v0 += __shfl_xor_sync(0xffffffffu, v0, o);
            v1 += __shfl_xor_sync(0xffffffffu, v1, o);
            v2 += __shfl_xor_sync(0xffffffffu, v2, o);
            v3 += __shfl_xor_sync(0xffffffffu, v3, o);
        }
        if (lane == 0) { s_dot[0] = v0; s_dot[1] = v1; s_dot[2] = v2; s_dot[3] = v3; }
    }

    // ---- Phase 2: confidences (warps 1..4, one per logits set) ----
    if (warp >= 1 && warp <= 4) {
        const int q = warp - 1;
        const float* lg = ls[q] + (size_t)b * NCLS;
        const bool v0 = lane < NCLS;
        const bool v1 = (lane + 32) < NCLS;
        float a0 = v0 ? lg[lane]      : -1e30f;
        float a1 = v1 ? lg[lane + 32] : -1e30f;
        float m = fmaxf(a0, a1);
#pragma unroll
        for (int o = 16; o > 0; o >>= 1)
            m = fmaxf(m, __shfl_xor_sync(0xffffffffu, m, o));
        float e0 = v0 ? expf(a0 - m) : 0.f;
        float e1 = v1 ? expf(a1 - m) : 0.f;
        float s = e0 + e1;
#pragma unroll
        for (int o = 16; o > 0; o >>= 1)
            s += __shfl_xor_sync(0xffffffffu, s, o);
        const float inv = 1.f / s;           // == max_p (softmax of the max logit)
        float p0 = e0 * inv, p1 = e1 * inv;
        float t = 0.f;
        if (v0) t += p0 * logf(p0 + 1e-8f);
        if (v1) t += p1 * logf(p1 + 1e-8f);
#pragma unroll
        for (int o = 16; o > 0; o >>= 1)
            t += __shfl_xor_sync(0xffffffffu, t, o);
        const float ent = -t;
        const float norm_ent = ent / logf((float)NCLS);
        if (lane == 0) s_conf[q] = inv * (1.f - norm_ent);
    }
    __syncthreads();

    // ---- Phase 3: 4-way softmax + sigmoid gates (thread 0) ----
    if (tid == 0) {
        float cm = fmaxf(fmaxf(s_conf[0], s_conf[1]), fmaxf(s_conf[2], s_conf[3]));
        float e[4], se = 0.f;
#pragma unroll
        for (int i = 0; i < 4; i++) { e[i] = expf(s_conf[i] - cm); se += e[i]; }
        const float inv = 1.f / se;
#pragma unroll
        for (int i = 0; i < 4; i++) {
            float nc = e[i] * inv;
            out[(size_t)i * NBATCH + b] = nc;              // norm_conf columns
            float u = 1.f / (1.f + expf(-(s_dot[i] + bs[i][0])));
            s_uf[i] = u * nc;
        }
    }
    __syncthreads();

    // ---- Phase 4: trans = (x + g[:,row,:]) * u_final ----
    const float4* gb = (const float4*)g + (size_t)b * TOT4;
    float4* ob = (float4*)(out + 4 * NBATCH) + (size_t)b * TOT4;
    for (int t = tid; t < TOT4; t += THREADS) {
        const int c = t >> 7;       // smem channel
        const int d = t & (ROW4 - 1);
        const int r = c_orow[c];
        const float sc = s_uf[c_gi[c]];
        float4 gv = gb[r * ROW4 + d];
        float4 xv = sx[t];
        float4 o;
        o.x = (xv.x + gv.x) * sc;
        o.y = (xv.y + gv.y) * sc;
        o.z = (xv.z + gv.z) * sc;
        o.w = (xv.w + gv.w) * sc;
        ob[r * ROW4 + d] = o;
    }
}

extern "C" void kernel_launch(void* const* d_in, const int* in_sizes, int n_in,
                              void* d_out, int out_size)
{
    const float* x1 = (const float*)d_in[0];
    const float* x2 = (const float*)d_in[1];
    const float* x3 = (const float*)d_in[2];
    const float* x4 = (const float*)d_in[3];
    const float* g  = (const float*)d_in[4];
    const float* l1 = (const float*)d_in[5];
    const float* l2 = (const float*)d_in[6];
    const float* l3 = (const float*)d_in[7];
    const float* l4 = (const float*)d_in[8];
    const float* W1 = (const float*)d_in[9];
    const float* b1 = (const float*)d_in[10];
    const float* W2 = (const float*)d_in[11];
    const float* b2 = (const float*)d_in[12];
    const float* W3 = (const float*)d_in[13];
    const float* b3 = (const float*)d_in[14];
    const float* W4 = (const float*)d_in[15];
    const float* b4 = (const float*)d_in[16];
    float* out = (float*)d_out;

    const int smem = 62 * 512 * (int)sizeof(float);   // 126976 B
    cudaFuncSetAttribute(lgl_fused_kernel,
                         cudaFuncAttributeMaxDynamicSharedMemorySize, smem);

    lgl_fused_kernel<<<NBATCH, THREADS, smem>>>(
        x1, x2, x3, x4, g, l1, l2, l3, l4,
        W1, b1, W2, b2, W3, b3, W4, b4, out);
}

// round 3
// speedup vs baseline: 1.5867x; 1.5867x over previous
#include <cuda_runtime.h>

#define NBATCH 2048
#define NCLS 62
#define THREADS 992           // 31 warps; 992*8 == 62*128 exactly
#define TOT4 (62 * 128)       // float4 per batch across all 62 channels

// output row r -> smem (concat) channel c  (corrected)
__constant__ int c_inv[62] = {
    1,0,2,3,4,12,5,6,7,8,9,10,11,13,14,15,          // rows 0-15
    30,31,32,33,34,16,17,18,19,35,36,37,38,39,      // rows 16-29
    20,21,22,23,40,41,42,43,44,                     // rows 30-38
    24,25,26,27,                                    // rows 39-42
    45,46,47,48,49,                                 // rows 43-47
    28,29,                                          // rows 48-49
    50,51,52,53,54,55,56,57,58,59,60,61             // rows 50-61
};
// smem (concat) channel c -> group index
__constant__ int c_gi[62] = {
    0,0,0,0,0,0,0,0,0,0,0,0,
    1,1,1,1,1,1,1,1,1,1,1,1,1,1,1,1,1,1,
    2,2,2,2,2,2,2,2,2,2,2,2,2,2,2,2,2,2,2,2,
    3,3,3,3,3,3,3,3,3,3,3,3
};

__global__ __launch_bounds__(THREADS, 1)
void lgl_fused_kernel(
    const float* __restrict__ x1, const float* __restrict__ x2,
    const float* __restrict__ x3, const float* __restrict__ x4,
    const float* __restrict__ g,
    const float* __restrict__ l1, const float* __restrict__ l2,
    const float* __restrict__ l3, const float* __restrict__ l4,
    const float* __restrict__ W1, const float* __restrict__ b1,
    const float* __restrict__ W2, const float* __restrict__ b2,
    const float* __restrict__ W3, const float* __restrict__ b3,
    const float* __restrict__ W4, const float* __restrict__ b4,
    float* __restrict__ out)
{
    extern __shared__ float4 sx[];        // 62*128 float4 = 126976 B (concat order)
    __shared__ float red[31][4];
    __shared__ float s_dot[4];
    __shared__ float s_conf[4];
    __shared__ float s_uf[4];

    const int b    = blockIdx.x;
    const int tid  = threadIdx.x;
    const int lane = tid & 31;
    const int warp = tid >> 5;

    const float4* x1v = (const float4*)x1;
    const float4* x2v = (const float4*)x2;
    const float4* x3v = (const float4*)x3;
    const float4* x4v = (const float4*)x4;
    const float4* w1v = (const float4*)W1;
    const float4* w2v = (const float4*)W2;
    const float4* w3v = (const float4*)W3;
    const float4* w4v = (const float4*)W4;

    // ---- Phase 1: stream x -> smem, accumulate dot(x_i, W_i). Fully unrolled. ----
    float p0 = 0.f, p1 = 0.f, p2 = 0.f, p3 = 0.f;
#pragma unroll
    for (int k = 0; k < 8; k++) {
        const int idx = tid + THREADS * k;     // concat float4 index 0..7935
        const int c = idx >> 7;
        const int d = idx & 127;
        const float4* xp;
        const float4* wp;
        if (c < 12)      { xp = x1v + ((size_t)b * 12 + c       ) * 128 + d; wp = w1v + (c       ) * 128 + d; }
        else if (c < 30) { xp = x2v + ((size_t)b * 18 + (c - 12)) * 128 + d; wp = w2v + (c - 12) * 128 + d; }
        else if (c < 50) { xp = x3v + ((size_t)b * 20 + (c - 30)) * 128 + d; wp = w3v + (c - 30) * 128 + d; }
        else             { xp = x4v + ((size_t)b * 12 + (c - 50)) * 128 + d; wp = w4v + (c - 50) * 128 + d; }
        float4 v = __ldcs(xp);
        float4 w = *wp;
        sx[idx] = v;
        float dp = v.x * w.x + v.y * w.y + v.z * w.z + v.w * w.w;
        p0 += (c < 12)              ? dp : 0.f;
        p1 += (c >= 12 && c < 30)   ? dp : 0.f;
        p2 += (c >= 30 && c < 50)   ? dp : 0.f;
        p3 += (c >= 50)             ? dp : 0.f;
    }

    // ---- Prefetch g (linear in output space) BEFORE the scalar critical section ----
    const float4* gb = (const float4*)g + (size_t)b * TOT4;
    float4 gv[8];
#pragma unroll
    for (int k = 0; k < 8; k++)
        gv[k] = __ldcs(gb + tid + THREADS * k);

    // ---- Reduce the 4 dot products ----
#pragma unroll
    for (int o = 16; o > 0; o >>= 1) {
        p0 += __shfl_xor_sync(0xffffffffu, p0, o);
        p1 += __shfl_xor_sync(0xffffffffu, p1, o);
        p2 += __shfl_xor_sync(0xffffffffu, p2, o);
        p3 += __shfl_xor_sync(0xffffffffu, p3, o);
    }
    if (lane == 0) { red[warp][0] = p0; red[warp][1] = p1; red[warp][2] = p2; red[warp][3] = p3; }
    __syncthreads();

    if (warp == 0) {
        const bool ok = lane < 31;
        float v0 = ok ? red[lane][0] : 0.f;
        float v1 = ok ? red[lane][1] : 0.f;
        float v2 = ok ? red[lane][2] : 0.f;
        float v3 = ok ? red[lane][3] : 0.f;
#pragma unroll
        for (int o = 16; o > 0; o >>= 1) {
            v0 += __shfl_xor_sync(0xffffffffu, v0, o);
            v1 += __shfl_xor_sync(0xffffffffu, v1, o);
            v2 += __shfl_xor_sync(0xffffffffu, v2, o);
            v3 += __shfl_xor_sync(0xffffffffu, v3, o);
        }
        if (lane == 0) { s_dot[0] = v0; s_dot[1] = v1; s_dot[2] = v2; s_dot[3] = v3; }
    }

    // ---- Phase 2: confidences (warps 1..4, one per logits set) ----
    if (warp >= 1 && warp <= 4) {
        const int q = warp - 1;
        const float* lg = (q == 0 ? l1 : q == 1 ? l2 : q == 2 ? l3 : l4) + (size_t)b * NCLS;
        const bool v0 = lane < NCLS;
        const bool v1 = (lane + 32) < NCLS;
        float a0 = v0 ? lg[lane]      : -1e30f;
        float a1 = v1 ? lg[lane + 32] : -1e30f;
        float m = fmaxf(a0, a1);
#pragma unroll
        for (int o = 16; o > 0; o >>= 1)
            m = fmaxf(m, __shfl_xor_sync(0xffffffffu, m, o));
        float e0 = v0 ? expf(a0 - m) : 0.f;
        float e1 = v1 ? expf(a1 - m) : 0.f;
        float s = e0 + e1;
#pragma unroll
        for (int o = 16; o > 0; o >>= 1)
            s += __shfl_xor_sync(0xffffffffu, s, o);
        const float inv = 1.f / s;           // == max_p
        float pp0 = e0 * inv, pp1 = e1 * inv;
        float t = 0.f;
        if (v0) t += pp0 * logf(pp0 + 1e-8f);
        if (v1) t += pp1 * logf(pp1 + 1e-8f);
#pragma unroll
        for (int o = 16; o > 0; o >>= 1)
            t += __shfl_xor_sync(0xffffffffu, t, o);
        const float norm_ent = (-t) / logf((float)NCLS);
        if (lane == 0) s_conf[q] = inv * (1.f - norm_ent);
    }
    __syncthreads();

    // ---- Phase 3: 4-way softmax + sigmoid gates (thread 0) ----
    if (tid == 0) {
        float cm = fmaxf(fmaxf(s_conf[0], s_conf[1]), fmaxf(s_conf[2], s_conf[3]));
        float e[4], se = 0.f;
#pragma unroll
        for (int i = 0; i < 4; i++) { e[i] = expf(s_conf[i] - cm); se += e[i]; }
        const float inv = 1.f / se;
        const float bb[4] = { b1[0], b2[0], b3[0], b4[0] };
#pragma unroll
        for (int i = 0; i < 4; i++) {
            float nc = e[i] * inv;
            out[(size_t)i * NBATCH + b] = nc;              // norm_conf columns
            float u = 1.f / (1.f + expf(-(s_dot[i] + bb[i])));
            s_uf[i] = u * nc;
        }
    }
    __syncthreads();

    // ---- Phase 4: trans = (x + g)*u_final, linear in output space ----
    float4* ob = (float4*)(out + 4 * NBATCH) + (size_t)b * TOT4;
#pragma unroll
    for (int k = 0; k < 8; k++) {
        const int idx = tid + THREADS * k;     // output-space float4 index
        const int r = idx >> 7;
        const int d = idx & 127;
        const int c = c_inv[r];
        const float sc = s_uf[c_gi[c]];
        float4 xv = sx[c * 128 + d];
        float4 o;
        o.x = (xv.x + gv[k].x) * sc;
        o.y = (xv.y + gv[k].y) * sc;
        o.z = (xv.z + gv[k].z) * sc;
        o.w = (xv.w + gv[k].w) * sc;
        __stcs(ob + idx, o);
    }
}

extern "C" void kernel_launch(void* const* d_in, const int* in_sizes, int n_in,
                              void* d_out, int out_size)
{
    const float* x1 = (const float*)d_in[0];
    const float* x2 = (const float*)d_in[1];
    const float* x3 = (const float*)d_in[2];
    const float* x4 = (const float*)d_in[3];
    const float* g  = (const float*)d_in[4];
    const float* l1 = (const float*)d_in[5];
    const float* l2 = (const float*)d_in[6];
    const float* l3 = (const float*)d_in[7];
    const float* l4 = (const float*)d_in[8];
    const float* W1 = (const float*)d_in[9];
    const float* b1 = (const float*)d_in[10];
    const float* W2 = (const float*)d_in[11];
    const float* b2 = (const float*)d_in[12];
    const float* W3 = (const float*)d_in[13];
    const float* b3 = (const float*)d_in[14];
    const float* W4 = (const float*)d_in[15];
    const float* b4 = (const float*)d_in[16];
    float* out = (float*)d_out;

    const int smem = 62 * 512 * (int)sizeof(float);   // 126976 B
    cudaFuncSetAttribute(lgl_fused_kernel,
                         cudaFuncAttributeMaxDynamicSharedMemorySize, smem);

    lgl_fused_kernel<<<NBATCH, THREADS, smem>>>(
        x1, x2, x3, x4, g, l1, l2, l3, l4,
        W1, b1, W2, b2, W3, b3, W4, b4, out);
}